// round 8
// baseline (speedup 1.0000x reference)
#include <cuda_runtime.h>
#include <cuda_bf16.h>
#include <cstdint>

// DescriptorLoss, single-pass bf16 HMMA (512 thr, 32x32 warp tiles), fused reduce.
//   dot[b,p,q] = sum_d D0[b,d,p]*D1[b,d,q]
//   loss = mean(mask ? relu(1-dot)*250 : relu(dot-0.2))

#define HW    4096
#define DDIM  128
#define NB    2
#define BM    128
#define BN    128
#define NQT   (HW / BN)          // 32
#define NPT   (HW / BM)          // 32
#define NPART (NB * NPT * NQT)   // 2048

#define LDK   136                // padded k-stride (bf16 elems), 272 B rows

#define SM_A   0
#define SM_B   (BM * LDK * 2)               // 34816
#define SM_RED (SM_B + BN * LDK * 2)        // 69632
#define SM_TOT (SM_RED + 512 * 4)           // 71680

__device__ __nv_bfloat16 g_d0t[(size_t)NB * HW * DDIM];  // [b][hw][d]
__device__ __nv_bfloat16 g_d1t[(size_t)NB * HW * DDIM];
__device__ float g_partials[NPART];
__device__ unsigned int g_count;                          // zero-init

// ---------- stage 1: convert + transpose ----------
__global__ __launch_bounds__(256)
void conv_kernel(const float* __restrict__ d0, const float* __restrict__ d1)
{
    __shared__ float tile[32][33];
    const int which = blockIdx.z & 1;
    const int b     = blockIdx.z >> 1;
    const float* src = (which ? d1 : d0) + (size_t)b * DDIM * HW;
    __nv_bfloat16* dst = (which ? g_d1t : g_d0t) + (size_t)b * HW * DDIM;

    const int hw0 = blockIdx.x * 32;
    const int dd0 = blockIdx.y * 32;
    const int tx = threadIdx.x, ty = threadIdx.y;   // 32 x 8

    #pragma unroll
    for (int j = 0; j < 4; j++)
        tile[ty + 8 * j][tx] = src[(size_t)(dd0 + ty + 8 * j) * HW + hw0 + tx];
    __syncthreads();
    #pragma unroll
    for (int j = 0; j < 4; j++)
        dst[(size_t)(hw0 + ty + 8 * j) * DDIM + dd0 + tx] =
            __float2bfloat16(tile[tx][ty + 8 * j]);
}

// ---------- stage 2: GEMM + fused loss + fused final reduce ----------
__global__ __launch_bounds__(512, 2)
void desc_loss_hmma_kernel(const int* __restrict__ mask, float* __restrict__ out)
{
    extern __shared__ char smem[];
    __nv_bfloat16* Asm = (__nv_bfloat16*)(smem + SM_A);
    __nv_bfloat16* Bsm = (__nv_bfloat16*)(smem + SM_B);
    float*         red = (float*)(smem + SM_RED);

    const int tid = threadIdx.x;
    const int wid = tid >> 5;
    const int lid = tid & 31;
    const int g   = lid >> 2;      // 0..7
    const int t   = lid & 3;       // 0..3

    const int b  = blockIdx.z;
    const int p0 = blockIdx.y * BM;
    const int q0 = blockIdx.x * BN;

    // prologue: bf16 scratch -> smem, 16B chunks (conflict-free)
    {
        const __nv_bfloat16* gA = g_d0t + (size_t)b * HW * DDIM + (size_t)p0 * DDIM;
        const __nv_bfloat16* gB = g_d1t + (size_t)b * HW * DDIM + (size_t)q0 * DDIM;
        #pragma unroll
        for (int it = 0; it < 4; it++) {
            int i = it * 512 + tid;
            int r = i >> 4;          // 0..127
            int c = i & 15;          // 16B chunk
            uint4 va = *(const uint4*)(gA + (size_t)r * DDIM + c * 8);
            uint4 vb = *(const uint4*)(gB + (size_t)r * DDIM + c * 8);
            *(uint4*)((char*)Asm + r * (LDK * 2) + c * 16) = va;
            *(uint4*)((char*)Bsm + r * (LDK * 2) + c * 16) = vb;
        }
    }
    __syncthreads();

    // 16 warps = 4(m) x 4(n), warp tile 32x32
    const int wm = wid & 3;
    const int wn = wid >> 2;

    float acc[2][4][4];
    #pragma unroll
    for (int i = 0; i < 2; i++)
        #pragma unroll
        for (int j = 0; j < 4; j++)
            #pragma unroll
            for (int u = 0; u < 4; u++)
                acc[i][j][u] = 0.0f;

    #pragma unroll
    for (int s = 0; s < 8; s++) {
        const int k0 = s * 16;
        uint32_t af[2][4], bf[4][2];
        #pragma unroll
        for (int ti = 0; ti < 2; ti++) {
            const int r0 = wm * 32 + ti * 16;
            af[ti][0] = *(const uint32_t*)&Asm[(r0 + g) * LDK + k0 + 2 * t];
            af[ti][1] = *(const uint32_t*)&Asm[(r0 + g + 8) * LDK + k0 + 2 * t];
            af[ti][2] = *(const uint32_t*)&Asm[(r0 + g) * LDK + k0 + 2 * t + 8];
            af[ti][3] = *(const uint32_t*)&Asm[(r0 + g + 8) * LDK + k0 + 2 * t + 8];
        }
        #pragma unroll
        for (int tj = 0; tj < 4; tj++) {
            const int n0 = wn * 32 + tj * 8;
            bf[tj][0] = *(const uint32_t*)&Bsm[(n0 + g) * LDK + k0 + 2 * t];
            bf[tj][1] = *(const uint32_t*)&Bsm[(n0 + g) * LDK + k0 + 2 * t + 8];
        }
        #pragma unroll
        for (int ti = 0; ti < 2; ti++)
            #pragma unroll
            for (int tj = 0; tj < 4; tj++) {
                asm volatile(
                    "mma.sync.aligned.m16n8k16.row.col.f32.bf16.bf16.f32 "
                    "{%0,%1,%2,%3}, {%4,%5,%6,%7}, {%8,%9}, {%0,%1,%2,%3};"
                    : "+f"(acc[ti][tj][0]), "+f"(acc[ti][tj][1]),
                      "+f"(acc[ti][tj][2]), "+f"(acc[ti][tj][3])
                    : "r"(af[ti][0]), "r"(af[ti][1]), "r"(af[ti][2]), "r"(af[ti][3]),
                      "r"(bf[tj][0]), "r"(bf[tj][1]));
            }
    }

    // epilogue: fused hinge loss; mask loads batched ahead of the math per ti
    float lsum = 0.0f;
    {
        const int* mbase = mask + (size_t)b * HW * HW + q0;
        #pragma unroll
        for (int ti = 0; ti < 2; ti++) {
            const int pr0 = p0 + wm * 32 + ti * 16 + g;
            int2 m0[4], m1[4];
            #pragma unroll
            for (int tj = 0; tj < 4; tj++) {
                const int qc = wn * 32 + tj * 8 + 2 * t;
                m0[tj] = *(const int2*)(mbase + (size_t)pr0 * HW + qc);
                m1[tj] = *(const int2*)(mbase + (size_t)(pr0 + 8) * HW + qc);
            }
            #pragma unroll
            for (int tj = 0; tj < 4; tj++) {
                float dv, pos, neg;
                dv = acc[ti][tj][0];
                pos = fmaxf(0.0f, 1.0f - dv) * 250.0f; neg = fmaxf(0.0f, dv - 0.2f);
                lsum += m0[tj].x ? pos : neg;
                dv = acc[ti][tj][1];
                pos = fmaxf(0.0f, 1.0f - dv) * 250.0f; neg = fmaxf(0.0f, dv - 0.2f);
                lsum += m0[tj].y ? pos : neg;
                dv = acc[ti][tj][2];
                pos = fmaxf(0.0f, 1.0f - dv) * 250.0f; neg = fmaxf(0.0f, dv - 0.2f);
                lsum += m1[tj].x ? pos : neg;
                dv = acc[ti][tj][3];
                pos = fmaxf(0.0f, 1.0f - dv) * 250.0f; neg = fmaxf(0.0f, dv - 0.2f);
                lsum += m1[tj].y ? pos : neg;
            }
        }
    }

    // deterministic block reduction over 512 threads
    red[tid] = lsum;
    __syncthreads();
    #pragma unroll
    for (int s = 256; s > 0; s >>= 1) {
        if (tid < s) red[tid] += red[tid + s];
        __syncthreads();
    }
    if (tid == 0)
        g_partials[(b * NPT + blockIdx.y) * NQT + blockIdx.x] = red[0];

    // last CTA does the fixed-order final reduction
    __threadfence();
    __shared__ int is_last;
    if (tid == 0) {
        unsigned int v = atomicAdd(&g_count, 1u);
        is_last = (v == NPART - 1);
    }
    __syncthreads();
    if (is_last) {
        float s = (g_partials[tid] + g_partials[tid + 512])
                + (g_partials[tid + 1024] + g_partials[tid + 1536]);
        red[tid] = s;
        __syncthreads();
        #pragma unroll
        for (int st = 256; st > 0; st >>= 1) {
            if (tid < st) red[tid] += red[tid + st];
            __syncthreads();
        }
        if (tid == 0) {
            out[0] = red[0] * (1.0f / ((float)NB * (float)HW * (float)HW));
            g_count = 0;   // reset for next graph replay
        }
    }
}

extern "C" void kernel_launch(void* const* d_in, const int* in_sizes, int n_in,
                              void* d_out, int out_size)
{
    const float* d0   = (const float*)d_in[0];
    const float* d1   = (const float*)d_in[1];
    const int*   mask = (const int*)d_in[2];
    float*       out  = (float*)d_out;

    cudaFuncSetAttribute(desc_loss_hmma_kernel,
                         cudaFuncAttributeMaxDynamicSharedMemorySize, SM_TOT);

    conv_kernel<<<dim3(HW / 32, DDIM / 32, 2 * NB), dim3(32, 8)>>>(d0, d1);
    desc_loss_hmma_kernel<<<dim3(NQT, NPT, NB), 512, SM_TOT>>>(mask, out);
}

// round 9
// speedup vs baseline: 1.0331x; 1.0331x over previous
#include <cuda_runtime.h>
#include <cuda_bf16.h>
#include <cstdint>

// DescriptorLoss, single-pass bf16 HMMA + ldmatrix, fused last-block reduce.
//   dot[b,p,q] = sum_d D0[b,d,p]*D1[b,d,q]
//   loss = mean(mask ? relu(1-dot)*250 : relu(dot-0.2))

#define HW    4096
#define DDIM  128
#define NB    2
#define BM    128
#define BN    128
#define NQT   (HW / BN)          // 32
#define NPT   (HW / BM)          // 32
#define NPART (NB * NPT * NQT)   // 2048

#define LDK   136                // padded k-stride (bf16 elems), 272 B rows
#define LDKB  (LDK * 2)          // row pitch in bytes

#define SM_A   0
#define SM_B   (BM * LDKB)                  // 34816
#define SM_RED (SM_B + BN * LDKB)           // 69632
#define SM_TOT (SM_RED + 512 * 4)           // 71680

__device__ __nv_bfloat16 g_d0t[(size_t)NB * HW * DDIM];  // [b][hw][d]
__device__ __nv_bfloat16 g_d1t[(size_t)NB * HW * DDIM];
__device__ float g_partials[NPART];
__device__ unsigned int g_count;                          // zero-init

__device__ __forceinline__ uint32_t smem_u32(const void* p) {
    uint32_t a;
    asm("{ .reg .u64 t; cvta.to.shared.u64 t, %1; cvt.u32.u64 %0, t; }" : "=r"(a) : "l"(p));
    return a;
}

// ---------- stage 1: convert + transpose ----------
__global__ __launch_bounds__(256)
void conv_kernel(const float* __restrict__ d0, const float* __restrict__ d1)
{
    __shared__ float tile[32][33];
    const int which = blockIdx.z & 1;
    const int b     = blockIdx.z >> 1;
    const float* src = (which ? d1 : d0) + (size_t)b * DDIM * HW;
    __nv_bfloat16* dst = (which ? g_d1t : g_d0t) + (size_t)b * HW * DDIM;

    const int hw0 = blockIdx.x * 32;
    const int dd0 = blockIdx.y * 32;
    const int tx = threadIdx.x, ty = threadIdx.y;   // 32 x 8

    #pragma unroll
    for (int j = 0; j < 4; j++)
        tile[ty + 8 * j][tx] = src[(size_t)(dd0 + ty + 8 * j) * HW + hw0 + tx];
    __syncthreads();
    #pragma unroll
    for (int j = 0; j < 4; j++)
        dst[(size_t)(hw0 + ty + 8 * j) * DDIM + dd0 + tx] =
            __float2bfloat16(tile[tx][ty + 8 * j]);
}

// ---------- stage 2: GEMM + fused loss + fused final reduce ----------
__global__ __launch_bounds__(512, 2)
void desc_loss_hmma_kernel(const int* __restrict__ mask, float* __restrict__ out)
{
    extern __shared__ char smem[];
    float* red = (float*)(smem + SM_RED);

    const int tid = threadIdx.x;
    const int wid = tid >> 5;
    const int lid = tid & 31;
    const int g   = lid >> 2;      // 0..7
    const int t   = lid & 3;       // 0..3

    const int b  = blockIdx.z;
    const int p0 = blockIdx.y * BM;
    const int q0 = blockIdx.x * BN;

    // prologue: bf16 scratch -> smem, 16B chunks (conflict-free)
    {
        const __nv_bfloat16* gA = g_d0t + (size_t)b * HW * DDIM + (size_t)p0 * DDIM;
        const __nv_bfloat16* gB = g_d1t + (size_t)b * HW * DDIM + (size_t)q0 * DDIM;
        #pragma unroll
        for (int it = 0; it < 4; it++) {
            int i = it * 512 + tid;
            int r = i >> 4;          // 0..127
            int c = i & 15;          // 16B chunk
            uint4 va = *(const uint4*)(gA + (size_t)r * DDIM + c * 8);
            uint4 vb = *(const uint4*)(gB + (size_t)r * DDIM + c * 8);
            *(uint4*)(smem + SM_A + r * LDKB + c * 16) = va;
            *(uint4*)(smem + SM_B + r * LDKB + c * 16) = vb;
        }
    }
    __syncthreads();

    // 16 warps = 4(m) x 4(n), warp tile 32x32
    const int wm = wid & 3;
    const int wn = wid >> 2;

    // ldmatrix per-lane base addresses (k0 = 0); advance by 32 B per k-step.
    // A x4 (per ti): m0 rows r0..7@k0, m1 r0+8..15@k0, m2 r0..7@k0+8, m3 r0+8..15@k0+8
    const uint32_t sA = smem_u32(smem) + SM_A;
    const uint32_t sB = smem_u32(smem) + SM_B;
    const int arow = (lid & 7) + ((lid >> 3) & 1) * 8;    // row-in-16 block
    const int acol = ((lid >> 4) & 1) * 8;                // k offset 0/8
    uint32_t aAddr[2], bAddr[2];
    #pragma unroll
    for (int ti = 0; ti < 2; ti++)
        aAddr[ti] = sA + (uint32_t)(wm * 32 + ti * 16 + arow) * LDKB + acol * 2;
    // B x4 (per tj-pair h): m0 n0..7@k0, m1 n0..7@k0+8, m2 n0+8..15@k0, m3 n0+8..15@k0+8
    const int brow = (lid & 7) + ((lid >> 4) & 1) * 8;
    const int bcol = ((lid >> 3) & 1) * 8;
    #pragma unroll
    for (int h = 0; h < 2; h++)
        bAddr[h] = sB + (uint32_t)(wn * 32 + h * 16 + brow) * LDKB + bcol * 2;

    float acc[2][4][4];
    #pragma unroll
    for (int i = 0; i < 2; i++)
        #pragma unroll
        for (int j = 0; j < 4; j++)
            #pragma unroll
            for (int u = 0; u < 4; u++)
                acc[i][j][u] = 0.0f;

    #pragma unroll
    for (int s = 0; s < 8; s++) {
        const uint32_t koff = (uint32_t)s * 32;   // 16 bf16 = 32 B
        uint32_t af[2][4], bf[4][2];
        #pragma unroll
        for (int ti = 0; ti < 2; ti++)
            asm volatile("ldmatrix.sync.aligned.m8n8.x4.shared.b16 {%0,%1,%2,%3}, [%4];"
                         : "=r"(af[ti][0]), "=r"(af[ti][1]), "=r"(af[ti][2]), "=r"(af[ti][3])
                         : "r"(aAddr[ti] + koff));
        #pragma unroll
        for (int h = 0; h < 2; h++)
            asm volatile("ldmatrix.sync.aligned.m8n8.x4.shared.b16 {%0,%1,%2,%3}, [%4];"
                         : "=r"(bf[2 * h][0]), "=r"(bf[2 * h][1]),
                           "=r"(bf[2 * h + 1][0]), "=r"(bf[2 * h + 1][1])
                         : "r"(bAddr[h] + koff));
        #pragma unroll
        for (int ti = 0; ti < 2; ti++)
            #pragma unroll
            for (int tj = 0; tj < 4; tj++) {
                asm volatile(
                    "mma.sync.aligned.m16n8k16.row.col.f32.bf16.bf16.f32 "
                    "{%0,%1,%2,%3}, {%4,%5,%6,%7}, {%8,%9}, {%0,%1,%2,%3};"
                    : "+f"(acc[ti][tj][0]), "+f"(acc[ti][tj][1]),
                      "+f"(acc[ti][tj][2]), "+f"(acc[ti][tj][3])
                    : "r"(af[ti][0]), "r"(af[ti][1]), "r"(af[ti][2]), "r"(af[ti][3]),
                      "r"(bf[tj][0]), "r"(bf[tj][1]));
            }
    }

    // epilogue: fused hinge loss with mask (int32)
    float lsum = 0.0f;
    {
        const int* mbase = mask + (size_t)b * HW * HW + q0;
        #pragma unroll
        for (int ti = 0; ti < 2; ti++) {
            const int pr0 = p0 + wm * 32 + ti * 16 + g;
            #pragma unroll
            for (int tj = 0; tj < 4; tj++) {
                const int qc = wn * 32 + tj * 8 + 2 * t;
                int2 m0 = *(const int2*)(mbase + (size_t)pr0 * HW + qc);
                int2 m1 = *(const int2*)(mbase + (size_t)(pr0 + 8) * HW + qc);
                float dv, pos, neg;
                dv = acc[ti][tj][0];
                pos = fmaxf(0.0f, 1.0f - dv) * 250.0f; neg = fmaxf(0.0f, dv - 0.2f);
                lsum += m0.x ? pos : neg;
                dv = acc[ti][tj][1];
                pos = fmaxf(0.0f, 1.0f - dv) * 250.0f; neg = fmaxf(0.0f, dv - 0.2f);
                lsum += m0.y ? pos : neg;
                dv = acc[ti][tj][2];
                pos = fmaxf(0.0f, 1.0f - dv) * 250.0f; neg = fmaxf(0.0f, dv - 0.2f);
                lsum += m1.x ? pos : neg;
                dv = acc[ti][tj][3];
                pos = fmaxf(0.0f, 1.0f - dv) * 250.0f; neg = fmaxf(0.0f, dv - 0.2f);
                lsum += m1.y ? pos : neg;
            }
        }
    }

    // deterministic block reduction over 512 threads
    red[tid] = lsum;
    __syncthreads();
    #pragma unroll
    for (int s = 256; s > 0; s >>= 1) {
        if (tid < s) red[tid] += red[tid + s];
        __syncthreads();
    }

    // last CTA does the fixed-order final reduction (fence only on tid 0;
    // g_partials is written only by tid 0, already ordered after syncthreads)
    __shared__ int is_last;
    if (tid == 0) {
        g_partials[(b * NPT + blockIdx.y) * NQT + blockIdx.x] = red[0];
        __threadfence();
        unsigned int v = atomicAdd(&g_count, 1u);
        is_last = (v == NPART - 1);
    }
    __syncthreads();
    if (is_last) {
        float s = (g_partials[tid] + g_partials[tid + 512])
                + (g_partials[tid + 1024] + g_partials[tid + 1536]);
        red[tid] = s;
        __syncthreads();
        #pragma unroll
        for (int st = 256; st > 0; st >>= 1) {
            if (tid < st) red[tid] += red[tid + st];
            __syncthreads();
        }
        if (tid == 0) {
            out[0] = red[0] * (1.0f / ((float)NB * (float)HW * (float)HW));
            g_count = 0;   // reset for next graph replay
        }
    }
}

extern "C" void kernel_launch(void* const* d_in, const int* in_sizes, int n_in,
                              void* d_out, int out_size)
{
    const float* d0   = (const float*)d_in[0];
    const float* d1   = (const float*)d_in[1];
    const int*   mask = (const int*)d_in[2];
    float*       out  = (float*)d_out;

    cudaFuncSetAttribute(desc_loss_hmma_kernel,
                         cudaFuncAttributeMaxDynamicSharedMemorySize, SM_TOT);

    conv_kernel<<<dim3(HW / 32, DDIM / 32, 2 * NB), dim3(32, 8)>>>(d0, d1);
    desc_loss_hmma_kernel<<<dim3(NQT, NPT, NB), 512, SM_TOT>>>(mask, out);
}